// round 16
// baseline (speedup 1.0000x reference)
#include <cuda_runtime.h>
#include <math.h>

// DSAFTNKSPLLoss — n = 8192 fixed.
// zero : zero rank counters / tickets (also shifts the positional ncu capture
//        window so the profiled launch lands on pair_sym_kernel).
// prep : e = log(dur+1e-32) - theta.
// rank : rank(o) = #{p : e_p < e_o} via FLOAT compares, 8-way column-split
//        counting; LAST chunk block per row group scatters e_sorted/ev/th.
// pair : symmetric O(n^2/2); sorted => d = e_j - e_i >= 0 for i<j. cdf tail
//        A&S 26.2.16 reusing exp(-d^2/2); single rcp per packed body; masked
//        blocks skip fully-sub-diagonal sub-tiles. 64x256 tiles, ib<=4jb+3.
//        launch_bounds(256,5): occupancy push (pair is latency-bound).
// fin  : coalesced segmented reduction + per-element loss; LAST block
//        (parity ticket) reproduces the reduction tree and writes the scalar.

#define NV 8192
#define ROWS_R 8
#define CHUNKS_R 8

typedef unsigned long long ull;

__device__ int      g_rank[NV];
__device__ int      g_done[NV / ROWS_R];
__device__ unsigned g_done2;
__device__ float    g_e[NV];
__device__ float    g_es[NV];
__device__ float    g_ev[NV];
__device__ float    g_th[NV];
__device__ float    g_prow_c[32 * NV];    // [jb][i]
__device__ float    g_prow_s[32 * NV];
__device__ float    g_pcol_c[128 * NV];   // [ib][j]
__device__ float    g_pcol_s[128 * NV];
__device__ float    g_rowloss[NV];

// ---------- f32x2 helpers ----------
static __device__ __forceinline__ ull pk(float a, float b) {
    ull r; asm("mov.b64 %0, {%1, %2};" : "=l"(r) : "f"(a), "f"(b)); return r;
}
static __device__ __forceinline__ float lof(ull x) {
    return __uint_as_float((unsigned)(x & 0xffffffffu));
}
static __device__ __forceinline__ float hif(ull x) {
    return __uint_as_float((unsigned)(x >> 32));
}
static __device__ __forceinline__ ull add2(ull a, ull b) {
    ull r; asm("add.rn.f32x2 %0, %1, %2;" : "=l"(r) : "l"(a), "l"(b)); return r;
}
static __device__ __forceinline__ ull mul2(ull a, ull b) {
    ull r; asm("mul.rn.f32x2 %0, %1, %2;" : "=l"(r) : "l"(a), "l"(b)); return r;
}
static __device__ __forceinline__ ull fma2(ull a, ull b, ull c) {
    ull r; asm("fma.rn.f32x2 %0, %1, %2, %3;" : "=l"(r) : "l"(a), "l"(b), "l"(c)); return r;
}
static __device__ __forceinline__ float ex2a(float x) {
    float r; asm("ex2.approx.f32 %0, %1;" : "=f"(r) : "f"(x)); return r;
}
static __device__ __forceinline__ float rcpa(float x) {
    float r; asm("rcp.approx.f32 %0, %1;" : "=f"(r) : "f"(x)); return r;
}

__global__ void zero_kernel() {
    int i = blockIdx.x * blockDim.x + threadIdx.x;
    if (i < NV) g_rank[i] = 0;
    if (i < NV / ROWS_R) g_done[i] = 0;
    if (i == 0) g_done2 = 0u;
}

__global__ void prep_kernel(const float* __restrict__ log_h,
                            const float* __restrict__ dur) {
    int i = blockIdx.x * blockDim.x + threadIdx.x;
    if (i >= NV) return;
    g_e[i] = logf(dur[i] + 1e-32f) - log_h[i];
}

__global__ void __launch_bounds__(32) rank_kernel(const float* __restrict__ log_h,
                                                  const int* __restrict__ events) {
    const int lane = threadIdx.x;
    const int grp = blockIdx.x / CHUNKS_R;
    const int r0 = grp * ROWS_R;
    const int p0 = (blockIdx.x % CHUNKS_R) * (NV / CHUNKS_R);

    float eo[ROWS_R];
    int cnt[ROWS_R];
#pragma unroll
    for (int m = 0; m < ROWS_R; m++) { eo[m] = g_e[r0 + m]; cnt[m] = 0; }

    const float4* ep4 = (const float4*)&g_e[p0];
#pragma unroll 2
    for (int t = 0; t < NV / CHUNKS_R / 128; t++) {
        float4 v = __ldg(&ep4[lane + t * 32]);
#pragma unroll
        for (int m = 0; m < ROWS_R; m++) {
            cnt[m] += (v.x < eo[m]);
            cnt[m] += (v.y < eo[m]);
            cnt[m] += (v.z < eo[m]);
            cnt[m] += (v.w < eo[m]);
        }
    }

#pragma unroll
    for (int m = 0; m < ROWS_R; m++)
        cnt[m] = __reduce_add_sync(0xffffffffu, cnt[m]);

    if (lane < ROWS_R) atomicAdd(&g_rank[r0 + lane], cnt[lane]);
    __threadfence();

    int tk = 0;
    if (lane == 0) tk = atomicAdd(&g_done[grp], 1);
    tk = __shfl_sync(0xffffffffu, tk, 0);
    if (tk == CHUNKS_R - 1) {       // last chunk for this row group: scatter
        __threadfence();
        if (lane < ROWS_R) {
            int o = r0 + lane;
            int r = g_rank[o];
            g_es[r] = g_e[o];
            g_ev[o] = (float)__ldg(&events[r]);
            g_th[o] = __ldg(&log_h[r]);
        }
    }
}

// ---------------- symmetric pair kernel ----------------
template <bool MASKED>
static __device__ __forceinline__ void pair_work(int ib, int jb, int rskip,
                                                 int w, int lane, int tid,
                                                 float* smc, float* sms) {
    const int i0 = ib * 64 + w * 8;

    ull ner2[4], evr2[4], ci2[4], svi2[4];
#pragma unroll
    for (int m = 0; m < 4; m++) {
        ner2[m] = pk(-g_es[i0 + 2 * m], -g_es[i0 + 2 * m + 1]);
        evr2[m] = pk(g_ev[i0 + 2 * m], g_ev[i0 + 2 * m + 1]);
        ci2[m] = 0; svi2[m] = 0;
    }

    const float NEXP = -0.72134752044448f;   // -0.5 * log2(e)
    const ull NEXP2 = pk(NEXP, NEXP);
    const ull A2    = pk(0.33267f, 0.33267f);
    const ull ONE2  = pk(1.0f, 1.0f);
    // A&S 26.2.16, 1/sqrt(2pi) folded, NEGATED
    const ull C3n = pk(-0.37392780f, -0.37392780f);
    const ull C2n = pk( 0.04793993f,  0.04793993f);
    const ull C1n = pk(-0.17401208f, -0.17401208f);
    const ull HALF2 = pk(0.5f, 0.5f);
    const ull ABSM  = 0x7fffffff7fffffffULL;

    for (int st = 0; st < 4; st++) {
        const int jbase = jb * 256 + st * 64;
        ull cj2[2] = {0, 0}, svj2[2] = {0, 0};
        // Fully-sub-diagonal sub-tile (masked blocks only): all pairs have
        // j <= i -> zero contribution; skip compute, still write zero partials.
        const bool active = !MASKED || (st >= rskip);
        if (active) {
            ull ej2[2], vj2[2];
#pragma unroll
            for (int q = 0; q < 2; q++) {
                int j = jbase + q * 32 + lane;
                float ej = __ldg(&g_es[j]);
                float vj = __ldg(&g_ev[j]);
                ej2[q] = pk(ej, ej);
                vj2[q] = pk(vj, vj);
            }
#pragma unroll
            for (int m = 0; m < 4; m++) {
#pragma unroll
                for (int q = 0; q < 2; q++) {
                    ull d  = add2(ej2[q], ner2[m]);          // e_j - e_i
                    ull a  = mul2(d, mul2(d, NEXP2));
                    ull ex = pk(ex2a(lof(a)), ex2a(hif(a))); // exp(-d^2/2)
                    ull dp = MASKED ? (d & ABSM) : d;
                    ull den = fma2(dp, A2, ONE2);            // 1 + 0.33267 d
                    // ONE rcp for both halves: inv = 1/(dl*dh);
                    // t_lo = inv*dh, t_hi = inv*dl.
                    float dl = lof(den), dh = hif(den);
                    float inv = rcpa(dl * dh);
                    ull t  = pk(inv * dh, inv * dl);
                    ull p  = fma2(t, C3n, C2n);
                    p = fma2(t, p, C1n);
                    ull s  = fma2(ex, mul2(t, p), HALF2);    // 0.5 - q >= 0
                    if (MASKED) {
                        int j = jbase + q * 32 + lane;
                        ull m2 = pk((i0 + 2 * m     < j) ? 1.0f : 0.0f,
                                    (i0 + 2 * m + 1 < j) ? 1.0f : 0.0f);
                        ex = mul2(ex, m2);
                        s  = mul2(s, m2);
                    }
                    ci2[m]  = fma2(ex, vj2[q], ci2[m]);      // row i: K*ev_j
                    cj2[q]  = fma2(ex, evr2[m], cj2[q]);     // col j: K*ev_i
                    svi2[m] = add2(svi2[m], s);              // row i: -s (fin)
                    svj2[q] = add2(svj2[q], s);              // col j: +s (fin)
                }
            }
        }
#pragma unroll
        for (int q = 0; q < 2; q++) {
            smc[w * 64 + q * 32 + lane] = lof(cj2[q]) + hif(cj2[q]);
            sms[w * 64 + q * 32 + lane] = lof(svj2[q]) + hif(svj2[q]);
        }
        __syncthreads();
        if (tid < 64) {
            float sc = 0.0f, ss = 0.0f;
#pragma unroll
            for (int ww = 0; ww < 8; ww++) {
                sc += smc[ww * 64 + tid];
                ss += sms[ww * 64 + tid];
            }
            g_pcol_c[ib * NV + jbase + tid] = sc;
            g_pcol_s[ib * NV + jbase + tid] = ss;
        }
        __syncthreads();
    }

#pragma unroll
    for (int m = 0; m < 4; m++) {
#pragma unroll
        for (int off = 16; off > 0; off >>= 1) {
            ci2[m]  = add2(ci2[m],  __shfl_down_sync(0xffffffffu, ci2[m],  off));
            svi2[m] = add2(svi2[m], __shfl_down_sync(0xffffffffu, svi2[m], off));
        }
    }
    if (lane == 0) {
#pragma unroll
        for (int m = 0; m < 4; m++) {
            g_prow_c[jb * NV + i0 + 2 * m]     = lof(ci2[m]);
            g_prow_c[jb * NV + i0 + 2 * m + 1] = hif(ci2[m]);
            g_prow_s[jb * NV + i0 + 2 * m]     = lof(svi2[m]);
            g_prow_s[jb * NV + i0 + 2 * m + 1] = hif(svi2[m]);
        }
    }
}

__global__ void __launch_bounds__(256, 5) pair_sym_kernel() {
    __shared__ float smc[8 * 64];
    __shared__ float sms[8 * 64];
    const int tid = threadIdx.x;
    const int w = tid >> 5, lane = tid & 31;

    int id = blockIdx.x, jb = 0;
    while (id >= 4 * jb + 4) { id -= 4 * jb + 4; jb++; }
    const int ib = id;

    if (ib >= 4 * jb) pair_work<true >(ib, jb, ib - 4 * jb, w, lane, tid, smc, sms);
    else              pair_work<false>(ib, jb, 0, w, lane, tid, smc, sms);
}

// Block handles 32 consecutive elements (coalesced partial reads); 8 warps
// stride the partials dimension; smem merge in fixed warp order. The LAST
// block (parity ticket) then reproduces the reduction tree exactly.
__global__ void __launch_bounds__(256) finalize_kernel(float* __restrict__ out) {
    __shared__ float smc[8][32];
    __shared__ float sms[8][32];
    __shared__ int slast;
    __shared__ float smr[8];
    const int tid = threadIdx.x;
    const int lane = tid & 31;
    const int w = tid >> 5;
    const int k0 = blockIdx.x * 32;
    const int k = k0 + lane;

    const int jb0 = k0 >> 8;
    const int ibmax = 4 * jb0 + 3;

    float c = 0.0f, sv = 0.0f;
    for (int jb = jb0 + w; jb < 32; jb += 8) {
        c  += g_prow_c[jb * NV + k];
        sv -= g_prow_s[jb * NV + k];   // row role: cdf - 0.5 = -s
    }
    for (int ib = w; ib <= ibmax; ib += 8) {
        c  += g_pcol_c[ib * NV + k];
        sv += g_pcol_s[ib * NV + k];   // col role: cdf - 0.5 = +s
    }
    smc[w][lane] = c;
    sms[w][lane] = sv;
    __syncthreads();
    if (w == 0) {
        float cc = 0.0f, ss = 0.0f;
#pragma unroll
        for (int ww = 0; ww < 8; ww++) { cc += smc[ww][lane]; ss += sms[ww][lane]; }
        cc += g_ev[k];                 // diagonal: exp(0)*ev_k
        float cond = fmaf(cc, 0.3989422804014327f / 8192.0f, 8.192e-29f);
        float surv = fmaf(ss, 1.0f / 8192.0f, 0.5f);
        g_rowloss[k] = (logf(cond) - logf(surv) + g_th[k]) * g_ev[k];
    }

    // ---- inline final reduction: last block reproduces the tree ----
    __threadfence();
    if (tid == 0)
        slast = ((atomicAdd(&g_done2, 1u) & 255u) == 255u);
    __syncthreads();
    if (slast) {
        const float4* v = (const float4*)g_rowloss;
        float a = 0.0f;
#pragma unroll
        for (int t = 0; t < NV / 4 / 256; t++) {
            float4 x = v[tid + t * 256];
            a += (x.x + x.y) + (x.z + x.w);
        }
#pragma unroll
        for (int off = 16; off > 0; off >>= 1)
            a += __shfl_down_sync(0xffffffffu, a, off);
        if (lane == 0) smr[w] = a;
        __syncthreads();
        if (tid == 0) {
            float s = 0.0f;
#pragma unroll
            for (int ww = 0; ww < 8; ww++) s += smr[ww];
            out[0] = -s * (1.0f / 8192.0f);
        }
    }
}

extern "C" void kernel_launch(void* const* d_in, const int* in_sizes, int n_in,
                              void* d_out, int out_size) {
    const float* log_h  = (const float*)d_in[0];
    const float* dur    = (const float*)d_in[1];
    const int*   events = (const int*)d_in[2];
    float* out = (float*)d_out;

    zero_kernel<<<NV / 256, 256>>>();
    prep_kernel<<<NV / 256, 256>>>(log_h, dur);
    rank_kernel<<<(NV / ROWS_R) * CHUNKS_R, 32>>>(log_h, events);
    pair_sym_kernel<<<2112, 256>>>();
    finalize_kernel<<<NV / 32, 256>>>(out);
}

// round 17
// speedup vs baseline: 1.1501x; 1.1501x over previous
#include <cuda_runtime.h>
#include <math.h>

// DSAFTNKSPLLoss — n = 8192 fixed.
// prep : e = log(dur+1e-32) - theta; zero rank counters/tickets.
// rank : rank(o) = #{p : e_p < e_o} via FLOAT compares, 8-way column-split
//        counting; LAST chunk block per row group scatters e_sorted/ev/th.
// pair : symmetric O(n^2/2); sorted => d = e_j - e_i >= 0 for i<j. cdf tail
//        A&S 26.2.16 reusing exp(-d^2/2); single rcp per packed body; masked
//        blocks skip fully-sub-diagonal sub-tiles. 64x256 tiles, ib<=4jb+3.
//        launch_bounds(256,4): measured best (lb5 caps regs at 48 -> spills,
//        L1 47.8%, +6.4us total — do not raise occupancy via reg caps).
// fin  : coalesced segmented reduction + per-element loss; LAST block
//        (parity ticket) reproduces the reduction tree and writes the scalar.

#define NV 8192
#define ROWS_R 8
#define CHUNKS_R 8

typedef unsigned long long ull;

__device__ int      g_rank[NV];
__device__ int      g_done[NV / ROWS_R];
__device__ unsigned g_done2;
__device__ float    g_e[NV];
__device__ float    g_es[NV];
__device__ float    g_ev[NV];
__device__ float    g_th[NV];
__device__ float    g_prow_c[32 * NV];    // [jb][i]
__device__ float    g_prow_s[32 * NV];
__device__ float    g_pcol_c[128 * NV];   // [ib][j]
__device__ float    g_pcol_s[128 * NV];
__device__ float    g_rowloss[NV];

// ---------- f32x2 helpers ----------
static __device__ __forceinline__ ull pk(float a, float b) {
    ull r; asm("mov.b64 %0, {%1, %2};" : "=l"(r) : "f"(a), "f"(b)); return r;
}
static __device__ __forceinline__ float lof(ull x) {
    return __uint_as_float((unsigned)(x & 0xffffffffu));
}
static __device__ __forceinline__ float hif(ull x) {
    return __uint_as_float((unsigned)(x >> 32));
}
static __device__ __forceinline__ ull add2(ull a, ull b) {
    ull r; asm("add.rn.f32x2 %0, %1, %2;" : "=l"(r) : "l"(a), "l"(b)); return r;
}
static __device__ __forceinline__ ull mul2(ull a, ull b) {
    ull r; asm("mul.rn.f32x2 %0, %1, %2;" : "=l"(r) : "l"(a), "l"(b)); return r;
}
static __device__ __forceinline__ ull fma2(ull a, ull b, ull c) {
    ull r; asm("fma.rn.f32x2 %0, %1, %2, %3;" : "=l"(r) : "l"(a), "l"(b), "l"(c)); return r;
}
static __device__ __forceinline__ float ex2a(float x) {
    float r; asm("ex2.approx.f32 %0, %1;" : "=f"(r) : "f"(x)); return r;
}
static __device__ __forceinline__ float rcpa(float x) {
    float r; asm("rcp.approx.f32 %0, %1;" : "=f"(r) : "f"(x)); return r;
}

__global__ void prep_kernel(const float* __restrict__ log_h,
                            const float* __restrict__ dur) {
    int i = blockIdx.x * blockDim.x + threadIdx.x;
    if (i >= NV) return;
    g_e[i] = logf(dur[i] + 1e-32f) - log_h[i];
    g_rank[i] = 0;
    if (i < NV / ROWS_R) g_done[i] = 0;
    if (i == 0) g_done2 = 0u;
}

__global__ void __launch_bounds__(32) rank_kernel(const float* __restrict__ log_h,
                                                  const int* __restrict__ events) {
    const int lane = threadIdx.x;
    const int grp = blockIdx.x / CHUNKS_R;
    const int r0 = grp * ROWS_R;
    const int p0 = (blockIdx.x % CHUNKS_R) * (NV / CHUNKS_R);

    float eo[ROWS_R];
    int cnt[ROWS_R];
#pragma unroll
    for (int m = 0; m < ROWS_R; m++) { eo[m] = g_e[r0 + m]; cnt[m] = 0; }

    const float4* ep4 = (const float4*)&g_e[p0];
#pragma unroll 2
    for (int t = 0; t < NV / CHUNKS_R / 128; t++) {
        float4 v = __ldg(&ep4[lane + t * 32]);
#pragma unroll
        for (int m = 0; m < ROWS_R; m++) {
            cnt[m] += (v.x < eo[m]);
            cnt[m] += (v.y < eo[m]);
            cnt[m] += (v.z < eo[m]);
            cnt[m] += (v.w < eo[m]);
        }
    }

#pragma unroll
    for (int m = 0; m < ROWS_R; m++)
        cnt[m] = __reduce_add_sync(0xffffffffu, cnt[m]);

    if (lane < ROWS_R) atomicAdd(&g_rank[r0 + lane], cnt[lane]);
    __threadfence();

    int tk = 0;
    if (lane == 0) tk = atomicAdd(&g_done[grp], 1);
    tk = __shfl_sync(0xffffffffu, tk, 0);
    if (tk == CHUNKS_R - 1) {       // last chunk for this row group: scatter
        __threadfence();
        if (lane < ROWS_R) {
            int o = r0 + lane;
            int r = g_rank[o];
            g_es[r] = g_e[o];
            g_ev[o] = (float)__ldg(&events[r]);
            g_th[o] = __ldg(&log_h[r]);
        }
    }
}

// ---------------- symmetric pair kernel ----------------
template <bool MASKED>
static __device__ __forceinline__ void pair_work(int ib, int jb, int rskip,
                                                 int w, int lane, int tid,
                                                 float* smc, float* sms) {
    const int i0 = ib * 64 + w * 8;

    ull ner2[4], evr2[4], ci2[4], svi2[4];
#pragma unroll
    for (int m = 0; m < 4; m++) {
        ner2[m] = pk(-g_es[i0 + 2 * m], -g_es[i0 + 2 * m + 1]);
        evr2[m] = pk(g_ev[i0 + 2 * m], g_ev[i0 + 2 * m + 1]);
        ci2[m] = 0; svi2[m] = 0;
    }

    const float NEXP = -0.72134752044448f;   // -0.5 * log2(e)
    const ull NEXP2 = pk(NEXP, NEXP);
    const ull A2    = pk(0.33267f, 0.33267f);
    const ull ONE2  = pk(1.0f, 1.0f);
    // A&S 26.2.16, 1/sqrt(2pi) folded, NEGATED
    const ull C3n = pk(-0.37392780f, -0.37392780f);
    const ull C2n = pk( 0.04793993f,  0.04793993f);
    const ull C1n = pk(-0.17401208f, -0.17401208f);
    const ull HALF2 = pk(0.5f, 0.5f);
    const ull ABSM  = 0x7fffffff7fffffffULL;

#pragma unroll
    for (int st = 0; st < 4; st++) {
        const int jbase = jb * 256 + st * 64;
        ull cj2[2] = {0, 0}, svj2[2] = {0, 0};
        // Fully-sub-diagonal sub-tile (masked blocks only): all pairs have
        // j <= i -> zero contribution; skip compute, still write zero partials.
        const bool active = !MASKED || (st >= rskip);
        if (active) {
            ull ej2[2], vj2[2];
#pragma unroll
            for (int q = 0; q < 2; q++) {
                int j = jbase + q * 32 + lane;
                float ej = __ldg(&g_es[j]);
                float vj = __ldg(&g_ev[j]);
                ej2[q] = pk(ej, ej);
                vj2[q] = pk(vj, vj);
            }
#pragma unroll
            for (int m = 0; m < 4; m++) {
#pragma unroll
                for (int q = 0; q < 2; q++) {
                    ull d  = add2(ej2[q], ner2[m]);          // e_j - e_i
                    ull a  = mul2(d, mul2(d, NEXP2));
                    ull ex = pk(ex2a(lof(a)), ex2a(hif(a))); // exp(-d^2/2)
                    ull dp = MASKED ? (d & ABSM) : d;
                    ull den = fma2(dp, A2, ONE2);            // 1 + 0.33267 d
                    // ONE rcp for both halves: inv = 1/(dl*dh);
                    // t_lo = inv*dh, t_hi = inv*dl.
                    float dl = lof(den), dh = hif(den);
                    float inv = rcpa(dl * dh);
                    ull t  = pk(inv * dh, inv * dl);
                    ull p  = fma2(t, C3n, C2n);
                    p = fma2(t, p, C1n);
                    ull s  = fma2(ex, mul2(t, p), HALF2);    // 0.5 - q >= 0
                    if (MASKED) {
                        int j = jbase + q * 32 + lane;
                        ull m2 = pk((i0 + 2 * m     < j) ? 1.0f : 0.0f,
                                    (i0 + 2 * m + 1 < j) ? 1.0f : 0.0f);
                        ex = mul2(ex, m2);
                        s  = mul2(s, m2);
                    }
                    ci2[m]  = fma2(ex, vj2[q], ci2[m]);      // row i: K*ev_j
                    cj2[q]  = fma2(ex, evr2[m], cj2[q]);     // col j: K*ev_i
                    svi2[m] = add2(svi2[m], s);              // row i: -s (fin)
                    svj2[q] = add2(svj2[q], s);              // col j: +s (fin)
                }
            }
        }
#pragma unroll
        for (int q = 0; q < 2; q++) {
            smc[w * 64 + q * 32 + lane] = lof(cj2[q]) + hif(cj2[q]);
            sms[w * 64 + q * 32 + lane] = lof(svj2[q]) + hif(svj2[q]);
        }
        __syncthreads();
        if (tid < 64) {
            float sc = 0.0f, ss = 0.0f;
#pragma unroll
            for (int ww = 0; ww < 8; ww++) {
                sc += smc[ww * 64 + tid];
                ss += sms[ww * 64 + tid];
            }
            g_pcol_c[ib * NV + jbase + tid] = sc;
            g_pcol_s[ib * NV + jbase + tid] = ss;
        }
        __syncthreads();
    }

#pragma unroll
    for (int m = 0; m < 4; m++) {
#pragma unroll
        for (int off = 16; off > 0; off >>= 1) {
            ci2[m]  = add2(ci2[m],  __shfl_down_sync(0xffffffffu, ci2[m],  off));
            svi2[m] = add2(svi2[m], __shfl_down_sync(0xffffffffu, svi2[m], off));
        }
    }
    if (lane == 0) {
#pragma unroll
        for (int m = 0; m < 4; m++) {
            g_prow_c[jb * NV + i0 + 2 * m]     = lof(ci2[m]);
            g_prow_c[jb * NV + i0 + 2 * m + 1] = hif(ci2[m]);
            g_prow_s[jb * NV + i0 + 2 * m]     = lof(svi2[m]);
            g_prow_s[jb * NV + i0 + 2 * m + 1] = hif(svi2[m]);
        }
    }
}

__global__ void __launch_bounds__(256, 4) pair_sym_kernel() {
    __shared__ float smc[8 * 64];
    __shared__ float sms[8 * 64];
    const int tid = threadIdx.x;
    const int w = tid >> 5, lane = tid & 31;

    int id = blockIdx.x, jb = 0;
    while (id >= 4 * jb + 4) { id -= 4 * jb + 4; jb++; }
    const int ib = id;

    if (ib >= 4 * jb) pair_work<true >(ib, jb, ib - 4 * jb, w, lane, tid, smc, sms);
    else              pair_work<false>(ib, jb, 0, w, lane, tid, smc, sms);
}

// Block handles 32 consecutive elements (coalesced partial reads); 8 warps
// stride the partials dimension; smem merge in fixed warp order. The LAST
// block (parity ticket) then reproduces the reduction tree exactly.
__global__ void __launch_bounds__(256) finalize_kernel(float* __restrict__ out) {
    __shared__ float smc[8][32];
    __shared__ float sms[8][32];
    __shared__ int slast;
    __shared__ float smr[8];
    const int tid = threadIdx.x;
    const int lane = tid & 31;
    const int w = tid >> 5;
    const int k0 = blockIdx.x * 32;
    const int k = k0 + lane;

    const int jb0 = k0 >> 8;
    const int ibmax = 4 * jb0 + 3;

    float c = 0.0f, sv = 0.0f;
    for (int jb = jb0 + w; jb < 32; jb += 8) {
        c  += g_prow_c[jb * NV + k];
        sv -= g_prow_s[jb * NV + k];   // row role: cdf - 0.5 = -s
    }
    for (int ib = w; ib <= ibmax; ib += 8) {
        c  += g_pcol_c[ib * NV + k];
        sv += g_pcol_s[ib * NV + k];   // col role: cdf - 0.5 = +s
    }
    smc[w][lane] = c;
    sms[w][lane] = sv;
    __syncthreads();
    if (w == 0) {
        float cc = 0.0f, ss = 0.0f;
#pragma unroll
        for (int ww = 0; ww < 8; ww++) { cc += smc[ww][lane]; ss += sms[ww][lane]; }
        cc += g_ev[k];                 // diagonal: exp(0)*ev_k
        float cond = fmaf(cc, 0.3989422804014327f / 8192.0f, 8.192e-29f);
        float surv = fmaf(ss, 1.0f / 8192.0f, 0.5f);
        g_rowloss[k] = (logf(cond) - logf(surv) + g_th[k]) * g_ev[k];
    }

    // ---- inline final reduction: last block reproduces the tree ----
    __threadfence();
    if (tid == 0)
        slast = ((atomicAdd(&g_done2, 1u) & 255u) == 255u);
    __syncthreads();
    if (slast) {
        const float4* v = (const float4*)g_rowloss;
        float a = 0.0f;
#pragma unroll
        for (int t = 0; t < NV / 4 / 256; t++) {
            float4 x = v[tid + t * 256];
            a += (x.x + x.y) + (x.z + x.w);
        }
#pragma unroll
        for (int off = 16; off > 0; off >>= 1)
            a += __shfl_down_sync(0xffffffffu, a, off);
        if (lane == 0) smr[w] = a;
        __syncthreads();
        if (tid == 0) {
            float s = 0.0f;
#pragma unroll
            for (int ww = 0; ww < 8; ww++) s += smr[ww];
            out[0] = -s * (1.0f / 8192.0f);
        }
    }
}

extern "C" void kernel_launch(void* const* d_in, const int* in_sizes, int n_in,
                              void* d_out, int out_size) {
    const float* log_h  = (const float*)d_in[0];
    const float* dur    = (const float*)d_in[1];
    const int*   events = (const int*)d_in[2];
    float* out = (float*)d_out;

    prep_kernel<<<NV / 256, 256>>>(log_h, dur);
    rank_kernel<<<(NV / ROWS_R) * CHUNKS_R, 32>>>(log_h, events);
    pair_sym_kernel<<<2112, 256>>>();
    finalize_kernel<<<NV / 32, 256>>>(out);
}